// round 1
// baseline (speedup 1.0000x reference)
#include <cuda_runtime.h>
#include <math.h>

#define N 1024
#define H 8
#define OBS_LEN 8
#define PRED_LEN 12

// ---------------- scratch (device globals; no allocation) ----------------
__device__ float g_A[64 * 2];      // A = W1[:, :32] @ Wsp  -> [64,2]
__device__ float g_dconst[64];     // d = b1 + W1[:, :32] @ bsp
__device__ float g_posA[N * 64];   // posA[i][k] = A[k] . pos_i
__device__ float g_h[N * H];
__device__ float g_c[N * H];
__device__ float g_ctx[N * H];     // context (pool_h of prev step)
__device__ float g_outp[N * 2];    // output (position of prev step)
__device__ float g_u[N * 64];      // u_i, row-major [N][64]
__device__ float g_v[64 * N];      // v_j, k-major [64][N]

// ---------------- setup: A, dconst ----------------
__global__ void k_setup(const float* __restrict__ W1, const float* __restrict__ b1,
                        const float* __restrict__ Wsp, const float* __restrict__ bsp) {
    int k = threadIdx.x;
    if (k < 64) {
        float a0 = 0.f, a1 = 0.f, dd = b1[k];
        #pragma unroll 4
        for (int e = 0; e < 32; e++) {
            float w = W1[k * 48 + e];
            a0 = fmaf(w, Wsp[e * 2 + 0], a0);
            a1 = fmaf(w, Wsp[e * 2 + 1], a1);
            dd = fmaf(w, bsp[e], dd);
        }
        g_A[k * 2 + 0] = a0;
        g_A[k * 2 + 1] = a1;
        g_dconst[k] = dd;
    }
}

// ---------------- LSTM cell helper ----------------
template <int XI>
__device__ __forceinline__ void lstm_step(const float* x, float* h, float* c,
                                          const float* sWih, const float* sWhh,
                                          const float* sb) {
    float gates[32];
    #pragma unroll
    for (int g = 0; g < 32; g++) {
        float a = sb[g];
        #pragma unroll
        for (int m = 0; m < XI; m++) a = fmaf(sWih[g * XI + m], x[m], a);
        #pragma unroll
        for (int q = 0; q < 8; q++) a = fmaf(sWhh[g * 8 + q], h[q], a);
        gates[g] = a;
    }
    #pragma unroll
    for (int q = 0; q < 8; q++) {
        float ig = 1.f / (1.f + expf(-gates[q]));
        float fg = 1.f / (1.f + expf(-gates[8 + q]));
        float gg = tanhf(gates[16 + q]);
        float og = 1.f / (1.f + expf(-gates[24 + q]));
        float cn = fg * c[q] + ig * gg;
        c[q] = cn;
        h[q] = og * tanhf(cn);
    }
}

// ---------------- encoder: 8 LSTM steps per agent + posA + state init ----------------
__global__ void k_encoder(const float* __restrict__ obs_traj, const float* __restrict__ obs_pos,
                          const float* __restrict__ h0, const float* __restrict__ c0,
                          const float* __restrict__ We, const float* __restrict__ be,
                          const float* __restrict__ Wih, const float* __restrict__ Whh,
                          const float* __restrict__ bih, const float* __restrict__ bhh) {
    __shared__ float sWe[32], sbe[16], sWih[32 * 16], sWhh[32 * 8], sb[32];
    int tid = threadIdx.x;
    for (int idx = tid; idx < 32; idx += blockDim.x) sWe[idx] = We[idx];
    for (int idx = tid; idx < 16; idx += blockDim.x) sbe[idx] = be[idx];
    for (int idx = tid; idx < 512; idx += blockDim.x) sWih[idx] = Wih[idx];
    for (int idx = tid; idx < 256; idx += blockDim.x) sWhh[idx] = Whh[idx];
    for (int idx = tid; idx < 32; idx += blockDim.x) sb[idx] = bih[idx] + bhh[idx];
    __syncthreads();

    int i = blockIdx.x * blockDim.x + tid;
    if (i >= N) return;

    float h[8], c[8];
    #pragma unroll
    for (int q = 0; q < 8; q++) { h[q] = h0[i * 8 + q]; c[q] = c0[i * 8 + q]; }

    for (int t = 0; t < OBS_LEN; t++) {
        float px = obs_traj[(t * N + i) * 2 + 0];
        float py = obs_traj[(t * N + i) * 2 + 1];
        float x[16];
        #pragma unroll
        for (int m = 0; m < 16; m++) {
            float a = fmaf(sWe[m * 2 + 0], px, fmaf(sWe[m * 2 + 1], py, sbe[m]));
            x[m] = fmaxf(a, 0.f);
        }
        lstm_step<16>(x, h, c, sWih, sWhh, sb);
    }

    // decoder initial state: h = h_enc, c = 0, ctx = 0, out = 0
    #pragma unroll
    for (int q = 0; q < 8; q++) {
        g_h[i * 8 + q] = h[q];
        g_c[i * 8 + q] = 0.f;
        g_ctx[i * 8 + q] = 0.f;
    }
    g_outp[i * 2 + 0] = 0.f;
    g_outp[i * 2 + 1] = 0.f;

    float qx = obs_pos[((OBS_LEN - 1) * N + i) * 2 + 0];
    float qy = obs_pos[((OBS_LEN - 1) * N + i) * 2 + 1];
    #pragma unroll 8
    for (int k = 0; k < 64; k++)
        g_posA[i * 64 + k] = fmaf(g_A[k * 2 + 0], qx, g_A[k * 2 + 1] * qy);
}

// ---------------- decoder per-agent: input layer + LSTM + u/v vectors ----------------
__global__ void k_dec_lstm(const float* __restrict__ Wd, const float* __restrict__ bd,
                           const float* __restrict__ Wih, const float* __restrict__ Whh,
                           const float* __restrict__ bih, const float* __restrict__ bhh,
                           const float* __restrict__ W1) {
    __shared__ float sWd[160], sbd[16], sWih[512], sWhh[256], sb[32];
    __shared__ float sB[64 * 8], sC[64 * 8], sd[64];
    int tid = threadIdx.x;
    for (int idx = tid; idx < 160; idx += blockDim.x) sWd[idx] = Wd[idx];
    for (int idx = tid; idx < 16; idx += blockDim.x) sbd[idx] = bd[idx];
    for (int idx = tid; idx < 512; idx += blockDim.x) sWih[idx] = Wih[idx];
    for (int idx = tid; idx < 256; idx += blockDim.x) sWhh[idx] = Whh[idx];
    for (int idx = tid; idx < 32; idx += blockDim.x) sb[idx] = bih[idx] + bhh[idx];
    for (int idx = tid; idx < 512; idx += blockDim.x) {
        int k = idx >> 3, q = idx & 7;
        sB[idx] = W1[k * 48 + 32 + q];   // h_j block
        sC[idx] = W1[k * 48 + 40 + q];   // h_i block
    }
    for (int idx = tid; idx < 64; idx += blockDim.x) sd[idx] = g_dconst[idx];
    __syncthreads();

    int i = blockIdx.x * blockDim.x + tid;
    if (i >= N) return;

    float cat[10];
    #pragma unroll
    for (int q = 0; q < 8; q++) cat[q] = g_ctx[i * 8 + q];
    cat[8] = g_outp[i * 2 + 0];
    cat[9] = g_outp[i * 2 + 1];

    float x[16];
    #pragma unroll
    for (int m = 0; m < 16; m++) {
        float a = sbd[m];
        #pragma unroll
        for (int q = 0; q < 10; q++) a = fmaf(sWd[m * 10 + q], cat[q], a);
        x[m] = fmaxf(a, 0.f);
    }

    float h[8], c[8];
    #pragma unroll
    for (int q = 0; q < 8; q++) { h[q] = g_h[i * 8 + q]; c[q] = g_c[i * 8 + q]; }
    lstm_step<16>(x, h, c, sWih, sWhh, sb);
    #pragma unroll
    for (int q = 0; q < 8; q++) { g_h[i * 8 + q] = h[q]; g_c[i * 8 + q] = c[q]; }

    // u_i[k] = posA + h_i . C[k];  v_i[k] = -posA + h_i . B[k] + d[k]
    #pragma unroll 4
    for (int k = 0; k < 64; k++) {
        float pa = g_posA[i * 64 + k];
        float uu = pa, vv = sd[k] - pa;
        #pragma unroll
        for (int q = 0; q < 8; q++) {
            uu = fmaf(h[q], sC[k * 8 + q], uu);
            vv = fmaf(h[q], sB[k * 8 + q], vv);
        }
        g_u[i * 64 + k] = uu;
        g_v[k * N + i] = vv;
    }
}

// ---------------- pooling + heads: one block per agent i ----------------
__global__ void __launch_bounds__(256) k_pool(const int* __restrict__ nei,
                                              const float* __restrict__ eps,
                                              const float* __restrict__ W2,
                                              const float* __restrict__ b2,
                                              const float* __restrict__ Wm, const float* __restrict__ bm,
                                              const float* __restrict__ Wv, const float* __restrict__ bv,
                                              float* __restrict__ out, int t) {
    __shared__ float su[64];
    __shared__ float sW2[8 * 64];
    __shared__ float sb2[8];
    __shared__ float red[8 * 8];
    __shared__ float sph[8];

    int i = blockIdx.x;
    int tid = threadIdx.x;

    if (tid < 64) su[tid] = g_u[i * 64 + tid];
    for (int idx = tid; idx < 512; idx += 256) sW2[idx] = W2[idx];
    if (tid < 8) sb2[tid] = b2[tid];
    __syncthreads();

    const int* neirow = nei + (size_t)t * N * N + (size_t)i * N;
    int msk[4];
    #pragma unroll
    for (int m = 0; m < 4; m++) msk[m] = neirow[tid + m * 256];

    float acc[4][8];
    #pragma unroll
    for (int m = 0; m < 4; m++)
        #pragma unroll
        for (int o = 0; o < 8; o++) acc[m][o] = 0.f;

    const float4* su4 = (const float4*)su;
    const float4* sW24 = (const float4*)sW2;

    #pragma unroll 1
    for (int k4 = 0; k4 < 16; k4++) {
        float4 uk = su4[k4];
        float4 w[8];
        #pragma unroll
        for (int o = 0; o < 8; o++) w[o] = sW24[o * 16 + k4];
        #pragma unroll
        for (int kk = 0; kk < 4; kk++) {
            float uv = (&uk.x)[kk];
            const float* vrow = g_v + (size_t)(k4 * 4 + kk) * N;
            #pragma unroll
            for (int m = 0; m < 4; m++) {
                float z = uv + vrow[tid + m * 256];
                z = fmaxf(z, 0.f);
                #pragma unroll
                for (int o = 0; o < 8; o++)
                    acc[m][o] = fmaf(z, (&w[o].x)[kk], acc[m][o]);
            }
        }
    }

    // pool = relu(acc + b2); masked max (relu output >= 0 so 0-init is exact)
    float mx[8];
    #pragma unroll
    for (int o = 0; o < 8; o++) mx[o] = 0.f;
    #pragma unroll
    for (int m = 0; m < 4; m++) {
        if (msk[m] > 0) {
            #pragma unroll
            for (int o = 0; o < 8; o++)
                mx[o] = fmaxf(mx[o], fmaxf(acc[m][o] + sb2[o], 0.f));
        }
    }

    // warp reduce max
    #pragma unroll
    for (int off = 16; off > 0; off >>= 1)
        #pragma unroll
        for (int o = 0; o < 8; o++)
            mx[o] = fmaxf(mx[o], __shfl_xor_sync(0xffffffffu, mx[o], off));
    int w = tid >> 5, l = tid & 31;
    if (l == 0)
        #pragma unroll
        for (int o = 0; o < 8; o++) red[w * 8 + o] = mx[o];
    __syncthreads();
    if (tid < 8) {
        float m0 = red[tid];
        #pragma unroll
        for (int ww = 1; ww < 8; ww++) m0 = fmaxf(m0, red[ww * 8 + tid]);
        sph[tid] = m0;
        g_ctx[i * 8 + tid] = m0;   // context for next step
    }
    __syncthreads();

    if (tid == 0) {
        float h[8], ph[8];
        #pragma unroll
        for (int q = 0; q < 8; q++) { h[q] = g_h[i * 8 + q]; ph[q] = sph[q]; }
        #pragma unroll
        for (int r = 0; r < 2; r++) {
            float mu = bm[r];
            float lv = bv[r];
            #pragma unroll
            for (int q = 0; q < 4; q++) {
                mu = fmaf(Wm[r * 12 + q], h[q], mu);
                lv = fmaf(Wv[r * 12 + q], h[4 + q], lv);
            }
            #pragma unroll
            for (int q = 0; q < 8; q++) {
                mu = fmaf(Wm[r * 12 + 4 + q], ph[q], mu);
                lv = fmaf(Wv[r * 12 + 4 + q], ph[q], lv);
            }
            float e = eps[(t * N + i) * 2 + r];
            float pos = mu + e * expf(0.5f * lv);
            int base = (t * N + i) * 2 + r;
            out[base] = pos;                               // pred_traj
            out[PRED_LEN * N * 2 + base] = mu;             // mean
            out[2 * PRED_LEN * N * 2 + base] = lv;         // var (logvar)
            g_outp[i * 2 + r] = pos;                       // output for next step
        }
    }
}

// ---------------- launch ----------------
extern "C" void kernel_launch(void* const* d_in, const int* in_sizes, int n_in,
                              void* d_out, int out_size) {
    const float* obs_traj     = (const float*)d_in[0];
    const float* obs_traj_obs = (const float*)d_in[1];
    const int*   nei_index    = (const int*)d_in[2];
    // d_in[3] = nei_num_index (unused by reference)
    const float* h0   = (const float*)d_in[4];
    const float* c0   = (const float*)d_in[5];
    const float* eps  = (const float*)d_in[6];
    const float* We   = (const float*)d_in[7];
    const float* be   = (const float*)d_in[8];
    const float* Wih_t = (const float*)d_in[9];
    const float* Whh_t = (const float*)d_in[10];
    const float* bih_t = (const float*)d_in[11];
    const float* bhh_t = (const float*)d_in[12];
    const float* Wd   = (const float*)d_in[13];
    const float* bd   = (const float*)d_in[14];
    const float* Wih_p = (const float*)d_in[15];
    const float* Whh_p = (const float*)d_in[16];
    const float* bih_p = (const float*)d_in[17];
    const float* bhh_p = (const float*)d_in[18];
    const float* Wsp  = (const float*)d_in[19];
    const float* bsp  = (const float*)d_in[20];
    const float* W1   = (const float*)d_in[21];
    const float* b1   = (const float*)d_in[22];
    const float* W2   = (const float*)d_in[23];
    const float* b2   = (const float*)d_in[24];
    const float* Wm   = (const float*)d_in[25];
    const float* bm   = (const float*)d_in[26];
    const float* Wv   = (const float*)d_in[27];
    const float* bv   = (const float*)d_in[28];
    float* out = (float*)d_out;

    k_setup<<<1, 64>>>(W1, b1, Wsp, bsp);
    k_encoder<<<N / 256, 256>>>(obs_traj, obs_traj_obs, h0, c0,
                                We, be, Wih_t, Whh_t, bih_t, bhh_t);
    for (int t = 0; t < PRED_LEN; t++) {
        k_dec_lstm<<<N / 256, 256>>>(Wd, bd, Wih_p, Whh_p, bih_p, bhh_p, W1);
        k_pool<<<N, 256>>>(nei_index, eps, W2, b2, Wm, bm, Wv, bv, out, t);
    }
}

// round 3
// speedup vs baseline: 1.6227x; 1.6227x over previous
#include <cuda_runtime.h>
#include <math.h>

#define N 1024
#define H 8
#define OBS_LEN 8
#define PRED_LEN 12

typedef unsigned long long u64;

// ---------------- scratch (device globals; no allocation) ----------------
__device__ float g_h[N * H];
__device__ float g_c[N * H];
__device__ float g_posA[N * 64];    // posA[i][k] = A[k] . pos_i
__device__ float g_u[N * 64];       // u_i, row-major [N][64]
__device__ float g_v[2][64 * N];    // v_j, k-major, DOUBLE-BUFFERED (cross-block race fix)
__device__ float g_dconst[64];      // d = b1 + W1[:, :32] @ bsp

// ---------------- packed f32x2 helpers ----------------
__device__ __forceinline__ u64 pack2(float lo, float hi) {
    u64 r; asm("mov.b64 %0, {%1, %2};" : "=l"(r) : "f"(lo), "f"(hi)); return r;
}
__device__ __forceinline__ void unpack2(u64 v, float& lo, float& hi) {
    asm("mov.b64 {%0, %1}, %2;" : "=f"(lo), "=f"(hi) : "l"(v));
}
__device__ __forceinline__ void ffma2(u64& d, u64 a, u64 b) {
    asm("fma.rn.f32x2 %0, %1, %2, %0;" : "+l"(d) : "l"(a), "l"(b));
}

__device__ __forceinline__ float sigm(float x) { return 1.f / (1.f + expf(-x)); }

// ---------------- LSTM cell helper ----------------
__device__ __forceinline__ void lstm_step(const float* x, float* h, float* c,
                                          const float* sWih, const float* sWhh,
                                          const float* sb) {
    float gates[32];
    #pragma unroll
    for (int g = 0; g < 32; g++) {
        float a = sb[g];
        #pragma unroll
        for (int m = 0; m < 16; m++) a = fmaf(sWih[g * 16 + m], x[m], a);
        #pragma unroll
        for (int q = 0; q < 8; q++) a = fmaf(sWhh[g * 8 + q], h[q], a);
        gates[g] = a;
    }
    #pragma unroll
    for (int q = 0; q < 8; q++) {
        float ig = sigm(gates[q]);
        float fg = sigm(gates[8 + q]);
        float gg = tanhf(gates[16 + q]);
        float og = sigm(gates[24 + q]);
        float cn = fg * c[q] + ig * gg;
        c[q] = cn;
        h[q] = og * tanhf(cn);
    }
}

// ---------------- encoder: 8 LSTM steps + FIRST decoder LSTM + u/v ----------------
__global__ void __launch_bounds__(128) k_encoder(
        const float* __restrict__ obs_traj, const float* __restrict__ obs_pos,
        const float* __restrict__ h0, const float* __restrict__ c0,
        const float* __restrict__ We, const float* __restrict__ be,
        const float* __restrict__ WihT, const float* __restrict__ WhhT,
        const float* __restrict__ bihT, const float* __restrict__ bhhT,
        const float* __restrict__ bd,
        const float* __restrict__ WihP, const float* __restrict__ WhhP,
        const float* __restrict__ bihP, const float* __restrict__ bhhP,
        const float* __restrict__ W1, const float* __restrict__ b1,
        const float* __restrict__ Wsp, const float* __restrict__ bsp) {
    __shared__ float sWe[32], sbe[16], sWihT[512], sWhhT[256], sbT[32];
    __shared__ float sWihP[512], sWhhP[256], sbP[32], sbd[16];
    __shared__ float sB[512], sC[512], sA[128], sd[64];
    int tid = threadIdx.x;
    for (int idx = tid; idx < 32; idx += 128) sWe[idx] = We[idx];
    for (int idx = tid; idx < 16; idx += 128) { sbe[idx] = be[idx]; sbd[idx] = bd[idx]; }
    for (int idx = tid; idx < 512; idx += 128) { sWihT[idx] = WihT[idx]; sWihP[idx] = WihP[idx]; }
    for (int idx = tid; idx < 256; idx += 128) { sWhhT[idx] = WhhT[idx]; sWhhP[idx] = WhhP[idx]; }
    for (int idx = tid; idx < 32; idx += 128) { sbT[idx] = bihT[idx] + bhhT[idx];
                                               sbP[idx] = bihP[idx] + bhhP[idx]; }
    for (int idx = tid; idx < 512; idx += 128) {
        int k = idx >> 3, q = idx & 7;
        sB[idx] = W1[k * 48 + 32 + q];   // multiplies h_j  -> v
        sC[idx] = W1[k * 48 + 40 + q];   // multiplies h_i  -> u
    }
    if (tid < 64) {
        int k = tid;
        float a0 = 0.f, a1 = 0.f, dd = b1[k];
        #pragma unroll 4
        for (int e = 0; e < 32; e++) {
            float w = W1[k * 48 + e];
            a0 = fmaf(w, Wsp[e * 2 + 0], a0);
            a1 = fmaf(w, Wsp[e * 2 + 1], a1);
            dd = fmaf(w, bsp[e], dd);
        }
        sA[k * 2 + 0] = a0; sA[k * 2 + 1] = a1; sd[k] = dd;
        g_dconst[k] = dd;
    }
    __syncthreads();

    int i = blockIdx.x * 128 + tid;

    float h[8], c[8];
    #pragma unroll
    for (int q = 0; q < 8; q++) { h[q] = h0[i * 8 + q]; c[q] = c0[i * 8 + q]; }

    for (int t = 0; t < OBS_LEN; t++) {
        float px = obs_traj[(t * N + i) * 2 + 0];
        float py = obs_traj[(t * N + i) * 2 + 1];
        float x[16];
        #pragma unroll
        for (int m = 0; m < 16; m++)
            x[m] = fmaxf(fmaf(sWe[m * 2 + 0], px, fmaf(sWe[m * 2 + 1], py, sbe[m])), 0.f);
        lstm_step(x, h, c, sWihT, sWhhT, sbT);
    }

    // first decoder step: context=0, output=0 -> x = relu(bd)
    float x[16];
    #pragma unroll
    for (int m = 0; m < 16; m++) x[m] = fmaxf(sbd[m], 0.f);
    #pragma unroll
    for (int q = 0; q < 8; q++) c[q] = 0.f;
    lstm_step(x, h, c, sWihP, sWhhP, sbP);

    #pragma unroll
    for (int q = 0; q < 8; q++) { g_h[i * 8 + q] = h[q]; g_c[i * 8 + q] = c[q]; }

    float qx = obs_pos[((OBS_LEN - 1) * N + i) * 2 + 0];
    float qy = obs_pos[((OBS_LEN - 1) * N + i) * 2 + 1];
    #pragma unroll 4
    for (int k = 0; k < 64; k++) {
        float pa = fmaf(sA[k * 2 + 0], qx, sA[k * 2 + 1] * qy);
        g_posA[i * 64 + k] = pa;
        float uu = pa, vv = sd[k] - pa;
        #pragma unroll
        for (int q = 0; q < 8; q++) {
            uu = fmaf(h[q], sC[k * 8 + q], uu);
            vv = fmaf(h[q], sB[k * 8 + q], vv);
        }
        g_u[i * 64 + k] = uu;
        g_v[0][k * N + i] = vv;    // step 0 reads buffer 0
    }
}

// ---------------- pooling + heads + NEXT decoder step: one block per agent ----------------
__global__ void __launch_bounds__(256, 3) k_pool(
        const int* __restrict__ nei, const float* __restrict__ eps,
        const float* __restrict__ W2, const float* __restrict__ b2,
        const float* __restrict__ Wm, const float* __restrict__ bm,
        const float* __restrict__ Wv, const float* __restrict__ bv,
        const float* __restrict__ Wd, const float* __restrict__ bd,
        const float* __restrict__ WihP, const float* __restrict__ WhhP,
        const float* __restrict__ bihP, const float* __restrict__ bhhP,
        const float* __restrict__ W1,
        float* __restrict__ out, int t) {
    __shared__ float su[64];
    __shared__ u64 sW2d[512];       // [k][o], each entry (w,w)
    __shared__ float sb2[8];
    __shared__ float red[8 * 8];
    __shared__ float sph[8], spos[2], sx[16], sgate[32], sh[8];

    int i = blockIdx.x;
    int tid = threadIdx.x;

    if (tid < 64) su[tid] = g_u[i * 64 + tid];
    for (int idx = tid; idx < 512; idx += 256) {
        int k = idx >> 3, o = idx & 7;
        float w = W2[o * 64 + k];
        sW2d[idx] = pack2(w, w);
    }
    if (tid < 8) sb2[tid] = b2[tid];
    __syncthreads();

    // thread handles j = 4*tid .. 4*tid+3 (consecutive -> vector loads)
    const int4 msk = ((const int4*)(nei + (size_t)t * N * N + (size_t)i * N))[tid];

    u64 acc01[8], acc23[8];
    #pragma unroll
    for (int o = 0; o < 8; o++) { acc01[o] = 0ull; acc23[o] = 0ull; }

    const float4* vbase = (const float4*)(g_v[t & 1]);   // READ buffer (t&1)
    #pragma unroll 4
    for (int k = 0; k < 64; k++) {
        float4 v4 = vbase[k * (N / 4) + tid];
        float uk = su[k];
        float z0 = fmaxf(uk + v4.x, 0.f);
        float z1 = fmaxf(uk + v4.y, 0.f);
        float z2 = fmaxf(uk + v4.z, 0.f);
        float z3 = fmaxf(uk + v4.w, 0.f);
        u64 z01 = pack2(z0, z1);
        u64 z23 = pack2(z2, z3);
        const u64* wrow = sW2d + k * 8;
        #pragma unroll
        for (int o = 0; o < 8; o++) {
            u64 w = wrow[o];
            ffma2(acc01[o], z01, w);
            ffma2(acc23[o], z23, w);
        }
    }

    // masked max of relu(acc + b2); relu >= 0 so 0-init is exact
    float mx[8];
    #pragma unroll
    for (int o = 0; o < 8; o++) mx[o] = 0.f;
    #pragma unroll
    for (int o = 0; o < 8; o++) {
        float a0, a1, a2, a3;
        unpack2(acc01[o], a0, a1);
        unpack2(acc23[o], a2, a3);
        float bo = sb2[o];
        if (msk.x > 0) mx[o] = fmaxf(mx[o], fmaxf(a0 + bo, 0.f));
        if (msk.y > 0) mx[o] = fmaxf(mx[o], fmaxf(a1 + bo, 0.f));
        if (msk.z > 0) mx[o] = fmaxf(mx[o], fmaxf(a2 + bo, 0.f));
        if (msk.w > 0) mx[o] = fmaxf(mx[o], fmaxf(a3 + bo, 0.f));
    }

    #pragma unroll
    for (int off = 16; off > 0; off >>= 1)
        #pragma unroll
        for (int o = 0; o < 8; o++)
            mx[o] = fmaxf(mx[o], __shfl_xor_sync(0xffffffffu, mx[o], off));
    int w = tid >> 5, l = tid & 31;
    if (l == 0)
        #pragma unroll
        for (int o = 0; o < 8; o++) red[w * 8 + o] = mx[o];
    __syncthreads();

    if (tid < 8) {
        float m0 = red[tid];
        #pragma unroll
        for (int ww = 1; ww < 8; ww++) m0 = fmaxf(m0, red[ww * 8 + tid]);
        sph[tid] = m0;
    }
    __syncthreads();

    // heads: tid r in {0,1} computes mu/logvar/pos for coordinate r
    if (tid < 2) {
        int r = tid;
        float mu = bm[r], lv = bv[r];
        #pragma unroll
        for (int q = 0; q < 4; q++) {
            mu = fmaf(Wm[r * 12 + q], g_h[i * 8 + q], mu);
            lv = fmaf(Wv[r * 12 + q], g_h[i * 8 + 4 + q], lv);
        }
        #pragma unroll
        for (int q = 0; q < 8; q++) {
            mu = fmaf(Wm[r * 12 + 4 + q], sph[q], mu);
            lv = fmaf(Wv[r * 12 + 4 + q], sph[q], lv);
        }
        float e = eps[(t * N + i) * 2 + r];
        float pos = mu + e * expf(0.5f * lv);
        int base = (t * N + i) * 2 + r;
        out[base] = pos;
        out[PRED_LEN * N * 2 + base] = mu;
        out[2 * PRED_LEN * N * 2 + base] = lv;
        spos[r] = pos;
    }
    if (t == PRED_LEN - 1) return;   // uniform branch: last step has no successor
    __syncthreads();

    // ---- next decoder LSTM step (agent i only) ----
    if (tid < 16) {
        int m = tid;
        float a = bd[m];
        #pragma unroll
        for (int q = 0; q < 8; q++) a = fmaf(Wd[m * 10 + q], sph[q], a);
        a = fmaf(Wd[m * 10 + 8], spos[0], a);
        a = fmaf(Wd[m * 10 + 9], spos[1], a);
        sx[m] = fmaxf(a, 0.f);
    }
    __syncthreads();
    if (tid < 32) {
        int g = tid;
        float a = bihP[g] + bhhP[g];
        #pragma unroll
        for (int m = 0; m < 16; m++) a = fmaf(WihP[g * 16 + m], sx[m], a);
        #pragma unroll
        for (int q = 0; q < 8; q++) a = fmaf(WhhP[g * 8 + q], g_h[i * 8 + q], a);
        sgate[g] = a;
    }
    __syncthreads();
    if (tid < 8) {
        int q = tid;
        float ig = sigm(sgate[q]);
        float fg = sigm(sgate[8 + q]);
        float gg = tanhf(sgate[16 + q]);
        float og = sigm(sgate[24 + q]);
        float cn = fg * g_c[i * 8 + q] + ig * gg;
        float hn = og * tanhf(cn);
        g_c[i * 8 + q] = cn;
        g_h[i * 8 + q] = hn;
        sh[q] = hn;
    }
    __syncthreads();
    if (tid < 64) {
        int k = tid;
        float pa = g_posA[i * 64 + k];
        float uu = pa, vv = g_dconst[k] - pa;
        #pragma unroll
        for (int q = 0; q < 8; q++) {
            uu = fmaf(sh[q], W1[k * 48 + 40 + q], uu);
            vv = fmaf(sh[q], W1[k * 48 + 32 + q], vv);
        }
        g_u[i * 64 + k] = uu;
        g_v[(t + 1) & 1][k * N + i] = vv;   // WRITE buffer ((t+1)&1) -> no race
    }
}

// ---------------- launch ----------------
extern "C" void kernel_launch(void* const* d_in, const int* in_sizes, int n_in,
                              void* d_out, int out_size) {
    const float* obs_traj     = (const float*)d_in[0];
    const float* obs_traj_obs = (const float*)d_in[1];
    const int*   nei_index    = (const int*)d_in[2];
    const float* h0   = (const float*)d_in[4];
    const float* c0   = (const float*)d_in[5];
    const float* eps  = (const float*)d_in[6];
    const float* We   = (const float*)d_in[7];
    const float* be   = (const float*)d_in[8];
    const float* Wih_t = (const float*)d_in[9];
    const float* Whh_t = (const float*)d_in[10];
    const float* bih_t = (const float*)d_in[11];
    const float* bhh_t = (const float*)d_in[12];
    const float* Wd   = (const float*)d_in[13];
    const float* bd   = (const float*)d_in[14];
    const float* Wih_p = (const float*)d_in[15];
    const float* Whh_p = (const float*)d_in[16];
    const float* bih_p = (const float*)d_in[17];
    const float* bhh_p = (const float*)d_in[18];
    const float* Wsp  = (const float*)d_in[19];
    const float* bsp  = (const float*)d_in[20];
    const float* W1   = (const float*)d_in[21];
    const float* b1   = (const float*)d_in[22];
    const float* W2   = (const float*)d_in[23];
    const float* b2   = (const float*)d_in[24];
    const float* Wm   = (const float*)d_in[25];
    const float* bm   = (const float*)d_in[26];
    const float* Wv   = (const float*)d_in[27];
    const float* bv   = (const float*)d_in[28];
    float* out = (float*)d_out;

    k_encoder<<<N / 128, 128>>>(obs_traj, obs_traj_obs, h0, c0, We, be,
                                Wih_t, Whh_t, bih_t, bhh_t, bd,
                                Wih_p, Whh_p, bih_p, bhh_p, W1, b1, Wsp, bsp);
    for (int t = 0; t < PRED_LEN; t++) {
        k_pool<<<N, 256>>>(nei_index, eps, W2, b2, Wm, bm, Wv, bv,
                           Wd, bd, Wih_p, Whh_p, bih_p, bhh_p, W1, out, t);
    }
}